// round 1
// baseline (speedup 1.0000x reference)
#include <cuda_runtime.h>

// Problem: BATCH=8388608 samples, input [BATCH,2] f32 = angles (r1, r2).
// With entangle_strength == 0, the RZZ phase is a pure global per-amplitude
// phase with |phase| = 1, so it cancels in |psi|^2. The product state gives
// exactly <Z0> = cos(r1), <Z1> = cos(r2). Output [BATCH,2] f32, same layout
// as the input => elementwise cos over 16,777,216 floats.

static constexpr int N_TOTAL = 8388608 * 2;      // 16,777,216 floats
static constexpr int N_VEC4  = N_TOTAL / 4;      // 4,194,304 float4s
static constexpr int TPB     = 256;
static constexpr int BLOCKS  = N_VEC4 / TPB;     // 16,384 blocks, exact cover

__global__ __launch_bounds__(TPB)
void qfraud_cos_kernel(const float4* __restrict__ in, float4* __restrict__ out) {
    int i = blockIdx.x * TPB + threadIdx.x;      // always in-range: exact cover
    float4 v = in[i];
    float4 r;
    r.x = cosf(v.x);
    r.y = cosf(v.y);
    r.z = cosf(v.z);
    r.w = cosf(v.w);
    out[i] = r;
}

extern "C" void kernel_launch(void* const* d_in, const int* in_sizes, int n_in,
                              void* d_out, int out_size) {
    const float4* in  = (const float4*)d_in[0];
    float4*       out = (float4*)d_out;
    qfraud_cos_kernel<<<BLOCKS, TPB>>>(in, out);
}

// round 2
// speedup vs baseline: 1.1664x; 1.1664x over previous
#include <cuda_runtime.h>

// out[i] = cos(in[i]) elementwise over 16,777,216 f32 (see R1 derivation:
// entangle_strength==0 => <Z0>=cos(r1), <Z1>=cos(r2), same layout as input).
//
// Custom cos: Cody-Waite reduction by pi (2-term), parity via 2^23*1.5
// magic-number round, even deg-8 Taylor poly on [-pi/2, pi/2].
// Max abs error ~2.6e-5 << 1e-3 rel threshold.

static constexpr int N_TOTAL = 8388608 * 2;          // 16,777,216 floats
static constexpr int N_VEC4  = N_TOTAL / 4;          // 4,194,304 float4s
static constexpr int TPB     = 256;
static constexpr int VPT     = 2;                    // float4s per thread
static constexpr int BLOCKS  = N_VEC4 / (TPB * VPT); // 8,192 blocks, exact cover
static constexpr int STRIDE  = BLOCKS * TPB;         // 2,097,152

__device__ __forceinline__ float fast_cos(float x) {
    const float INV_PI = 0.3183098861837907f;
    const float PI_HI  = 3.14159274101257324f;        // float(pi)
    const float PI_LO  = -8.74227765734758577e-08f;   // pi - PI_HI
    const float MAGIC  = 12582912.0f;                 // 1.5 * 2^23

    float t = fmaf(x, INV_PI, MAGIC);                 // round(x/pi) in low mantissa bits
    int   k = __float_as_int(t);                      // bit 0 = parity of q
    float q = t - MAGIC;                              // q = round(x/pi) as float
    float r = fmaf(q, -PI_HI, x);
    r       = fmaf(q, -PI_LO, r);                     // r = x - q*pi, |r| <= pi/2

    float r2 = r * r;
    float p  = fmaf(r2, 2.48015873e-5f, -1.38888889e-3f);  // 1/8! , -1/6!
    p        = fmaf(r2, p, 4.16666667e-2f);                 // 1/4!
    p        = fmaf(r2, p, -0.5f);
    p        = fmaf(r2, p, 1.0f);                           // cos(r)

    // cos(x) = (-1)^q * cos(r): flip sign bit if q odd
    return __int_as_float(__float_as_int(p) ^ ((k & 1) << 31));
}

__device__ __forceinline__ float4 cos4(float4 v) {
    float4 r;
    r.x = fast_cos(v.x);
    r.y = fast_cos(v.y);
    r.z = fast_cos(v.z);
    r.w = fast_cos(v.w);
    return r;
}

__global__ __launch_bounds__(TPB)
void qfraud_cos_kernel(const float4* __restrict__ in, float4* __restrict__ out) {
    int i = blockIdx.x * TPB + threadIdx.x;
    // Batch both loads up front: 2 outstanding DRAM loads per thread (MLP=2)
    float4 v0 = in[i];
    float4 v1 = in[i + STRIDE];
    out[i]          = cos4(v0);
    out[i + STRIDE] = cos4(v1);
}

extern "C" void kernel_launch(void* const* d_in, const int* in_sizes, int n_in,
                              void* d_out, int out_size) {
    const float4* in  = (const float4*)d_in[0];
    float4*       out = (float4*)d_out;
    qfraud_cos_kernel<<<BLOCKS, TPB>>>(in, out);
}

// round 3
// speedup vs baseline: 1.2254x; 1.0506x over previous
#include <cuda_runtime.h>

// out[i] = cos(in[i]) elementwise over 16,777,216 f32 (entangle_strength==0
// => <Z0>=cos(r1), <Z1>=cos(r2), same layout as input).
//
// Cody-Waite reduction by pi + even deg-8 poly; max abs err ~2.6e-5.
// MLP=4 float4 loads per thread, streaming (evict-first) cache hints.

static constexpr int N_VEC4  = (8388608 * 2) / 4;     // 4,194,304 float4s
static constexpr int TPB     = 256;
static constexpr int VPT     = 4;                     // float4s per thread
static constexpr int BLOCKS  = N_VEC4 / (TPB * VPT);  // 4,096 blocks, exact cover
static constexpr int STRIDE  = BLOCKS * TPB;          // 1,048,576

__device__ __forceinline__ float fast_cos(float x) {
    const float INV_PI = 0.3183098861837907f;
    const float PI_HI  = 3.14159274101257324f;        // float(pi)
    const float PI_LO  = -8.74227765734758577e-08f;   // pi - PI_HI
    const float MAGIC  = 12582912.0f;                 // 1.5 * 2^23

    float t = fmaf(x, INV_PI, MAGIC);                 // round(x/pi) in low bits
    int   k = __float_as_int(t);                      // bit 0 = parity of q
    float q = t - MAGIC;
    float r = fmaf(q, -PI_HI, x);
    r       = fmaf(q, -PI_LO, r);                     // r = x - q*pi, |r|<=pi/2

    float r2 = r * r;
    float p  = fmaf(r2, 2.48015873e-5f, -1.38888889e-3f);
    p        = fmaf(r2, p, 4.16666667e-2f);
    p        = fmaf(r2, p, -0.5f);
    p        = fmaf(r2, p, 1.0f);                     // cos(r)

    return __int_as_float(__float_as_int(p) ^ ((k & 1) << 31));
}

__device__ __forceinline__ float4 cos4(float4 v) {
    float4 r;
    r.x = fast_cos(v.x);
    r.y = fast_cos(v.y);
    r.z = fast_cos(v.z);
    r.w = fast_cos(v.w);
    return r;
}

__global__ __launch_bounds__(TPB)
void qfraud_cos_kernel(const float4* __restrict__ in, float4* __restrict__ out) {
    int i = blockIdx.x * TPB + threadIdx.x;

    // Issue all 4 LDG.128 back-to-back: MLP=4 per thread, evict-first.
    float4 v0 = __ldcs(&in[i]);
    float4 v1 = __ldcs(&in[i + STRIDE]);
    float4 v2 = __ldcs(&in[i + 2 * STRIDE]);
    float4 v3 = __ldcs(&in[i + 3 * STRIDE]);

    __stcs(&out[i],              cos4(v0));
    __stcs(&out[i + STRIDE],     cos4(v1));
    __stcs(&out[i + 2 * STRIDE], cos4(v2));
    __stcs(&out[i + 3 * STRIDE], cos4(v3));
}

extern "C" void kernel_launch(void* const* d_in, const int* in_sizes, int n_in,
                              void* d_out, int out_size) {
    const float4* in  = (const float4*)d_in[0];
    float4*       out = (float4*)d_out;
    qfraud_cos_kernel<<<BLOCKS, TPB>>>(in, out);
}

// round 4
// speedup vs baseline: 1.2947x; 1.0565x over previous
#include <cuda_runtime.h>

// out[i] = cos(in[i]) elementwise over 16,777,216 f32 (entangle_strength==0
// => <Z0>=cos(r1), <Z1>=cos(r2), same layout as input).
//
// DRAM-floor regime (7.45 TB/s of 8 TB/s measured in R3). Use MUFU __cosf
// (~3 instr/elt, ~1e-6 abs err for |x|<~6, inputs are N(0,1)) to cut register
// pressure and issue load, structured as two MLP=2 chunks to keep L1tex-queue
// spread low while still covering DRAM latency.

static constexpr int N_VEC4  = (8388608 * 2) / 4;     // 4,194,304 float4s
static constexpr int TPB     = 256;
static constexpr int VPT     = 4;                     // float4s per thread
static constexpr int BLOCKS  = N_VEC4 / (TPB * VPT);  // 4,096 blocks, exact cover
static constexpr int STRIDE  = BLOCKS * TPB;          // 1,048,576

__device__ __forceinline__ float4 cos4(float4 v) {
    float4 r;
    r.x = __cosf(v.x);
    r.y = __cosf(v.y);
    r.z = __cosf(v.z);
    r.w = __cosf(v.w);
    return r;
}

__global__ __launch_bounds__(TPB)
void qfraud_cos_kernel(const float4* __restrict__ in, float4* __restrict__ out) {
    int i = blockIdx.x * TPB + threadIdx.x;

    // Chunk 1: MLP=2
    float4 v0 = __ldcs(&in[i]);
    float4 v1 = __ldcs(&in[i + STRIDE]);
    __stcs(&out[i],          cos4(v0));
    __stcs(&out[i + STRIDE], cos4(v1));

    // Chunk 2: MLP=2
    float4 v2 = __ldcs(&in[i + 2 * STRIDE]);
    float4 v3 = __ldcs(&in[i + 3 * STRIDE]);
    __stcs(&out[i + 2 * STRIDE], cos4(v2));
    __stcs(&out[i + 3 * STRIDE], cos4(v3));
}

extern "C" void kernel_launch(void* const* d_in, const int* in_sizes, int n_in,
                              void* d_out, int out_size) {
    const float4* in  = (const float4*)d_in[0];
    float4*       out = (float4*)d_out;
    qfraud_cos_kernel<<<BLOCKS, TPB>>>(in, out);
}